// round 12
// baseline (speedup 1.0000x reference)
#include <cuda_runtime.h>
#include <cuda_bf16.h>

// PolyLoss: polygon IoU loss (Sutherland-Hodgman clip + shoelace area).
// B=16, K=128, V=16, C=2V=32, H=W=256 (HW=65536). One thread per polygon pair.

#define NV 16
#define MAXN 64          // 4*V
#define NBLK 64
#define NTHR 32

__device__ float g_partials[2 * NBLK];

__device__ __forceinline__ float safef(float d) {
    return (d == 0.0f) ? 1.0f : d;
}

// Inside test: R = (c2-c1) x (q-c1) <= 0. Sign-critical: no FMA contraction,
// to match XLA's elementwise mul/sub as closely as possible.
__device__ __forceinline__ bool is_inside(float ex, float ey,
                                          float c1x, float c1y,
                                          float qx, float qy) {
    float a = __fmul_rn(ex, __fsub_rn(qy, c1y));
    float b = __fmul_rn(ey, __fsub_rn(qx, c1x));
    return __fsub_rn(a, b) <= 0.0f;
}

// Shoelace area for a fixed 16-gon, replicating the reference's extra
// (v0 -> v1) edge term (first edge counted twice).
__device__ __forceinline__ float area16(const float* x, const float* y) {
    float left = 0.0f, right = 0.0f;
#pragma unroll
    for (int i = 0; i < NV; i++) {
        int j = (i + 1) & (NV - 1);
        left  += x[i] * y[j];
        right += y[i] * x[j];
    }
    left  += x[0] * y[1];
    right += y[0] * x[1];
    return fabsf(0.5f * (right - left));
}

__global__ void __launch_bounds__(NTHR, 8)
poly_loss_kernel(const float* __restrict__ output,
                 const float* __restrict__ mask,
                 const int*   __restrict__ ind,
                 const float* __restrict__ target,
                 int B, int K, int HW) {
    const int t  = blockIdx.x * blockDim.x + threadIdx.x;
    const int BK = B * K;
    const int C  = 2 * NV;

    float iou_m = 0.0f;
    float mk    = 0.0f;

    if (t < BK) {
        // ---- Gather pred polygon (32 strided loads) & load target ----
        float ax[MAXN], ay[MAXN];   // ping
        float bx[MAXN], by[MAXN];   // pong
        float tx[NV],   ty[NV];

        const int b   = t / K;
        const int pos = ind[t];
        const float* obase = output + (size_t)b * C * HW + pos;
        const float* trow  = target + (size_t)t * C;

#pragma unroll
        for (int v = 0; v < NV; v++) {
            ax[v] = obase[(size_t)(2 * v)     * HW];
            ay[v] = obase[(size_t)(2 * v + 1) * HW];
            tx[v] = trow[2 * v];
            ty[v] = trow[2 * v + 1];
        }

        const float a_p = area16(ax, ay);
        const float a_g = area16(tx, ty);

        // ---- Sutherland-Hodgman: clip pred by each target edge ----
        // Edge e: c1 = tgt[(e-1) mod 16], c2 = tgt[e]  (matches jnp.roll(clip,1))
        int n = NV;
        float *sx = ax, *sy = ay, *dx_ = bx, *dy_ = by;

#pragma unroll 1
        for (int e = 0; e < NV; e++) {
            if (n <= 0) break;
            const float c1x = tx[(e + NV - 1) & (NV - 1)];
            const float c1y = ty[(e + NV - 1) & (NV - 1)];
            const float c2x = tx[e];
            const float c2y = ty[e];
            const float ex  = c2x - c1x;
            const float ey  = c2y - c1y;
            // Clip-edge line params (reference: m2 = dy34/_safe(dx34), b2 = p3.y - m2*p3.x)
            const float dx34 = c2x - c1x;
            const float dy34 = c2y - c1y;
            const float m2   = dy34 / safef(dx34);
            const float b2   = c1y - m2 * c1x;
            const bool  vert2 = (dx34 == 0.0f);

            int m = 0;
            float pxv = sx[n - 1], pyv = sy[n - 1];
            bool  ip  = is_inside(ex, ey, c1x, c1y, pxv, pyv);

#pragma unroll 1
            for (int i = 0; i < n; i++) {
                const float cxv = sx[i], cyv = sy[i];
                const bool  ic  = is_inside(ex, ey, c1x, c1y, cxv, cyv);

                if (ic != ip) {
                    // _intersection(prev, cur, c1, c2) — exact reference semantics
                    const float dx12 = cxv - pxv;
                    const float dy12 = cyv - pyv;
                    const float m1   = dy12 / safef(dx12);
                    const float b1   = pyv - m1 * pxv;
                    float X, Y;
                    if (dx12 == 0.0f) {          // vert1 wins
                        X = pxv;
                        Y = m2 * pxv + b2;
                    } else if (vert2) {          // vert2
                        X = c1x;
                        Y = m1 * c1x + b1;
                    } else {                     // general
                        X = (b2 - b1) / safef(m1 - m2);
                        Y = m1 * X + b1;
                    }
                    if (m < MAXN) { dx_[m] = X; dy_[m] = Y; }
                    m++;
                }
                if (ic) {
                    if (m < MAXN) { dx_[m] = cxv; dy_[m] = cyv; }
                    m++;
                }
                pxv = cxv; pyv = cyv; ip = ic;
            }

            n = (m < MAXN) ? m : MAXN;
            float* tp;
            tp = sx; sx = dx_; dx_ = tp;
            tp = sy; sy = dy_; dy_ = tp;
        }

        // ---- Clipped-polygon area (same doubled-first-edge formula) ----
        float a_i = 0.0f;
        if (n > 0) {
            float left = 0.0f, right = 0.0f;
#pragma unroll 1
            for (int i = 0; i < n; i++) {
                const int j = (i + 1 == n) ? 0 : (i + 1);
                left  += sx[i] * sy[j];
                right += sy[i] * sx[j];
            }
            const int i1 = (n > 1) ? 1 : 0;   // 1 % n
            left  += sx[0] * sy[i1];
            right += sy[0] * sx[i1];
            a_i = fabsf(0.5f * (right - left));
        }

        // ---- IoU ----
        const float inter = a_i + ((a_i == 0.0f) ? fminf(a_p, a_g) : 0.0f);
        const float uni   = a_g + a_p - inter;
        const float iou   = inter / (uni + 1e-6f);

        mk    = mask[t];
        iou_m = iou * mk;
    }

    // ---- Deterministic warp reduction (blockDim == 32) ----
#pragma unroll
    for (int o = 16; o > 0; o >>= 1) {
        iou_m += __shfl_down_sync(0xffffffffu, iou_m, o);
        mk    += __shfl_down_sync(0xffffffffu, mk, o);
    }
    if (threadIdx.x == 0) {
        g_partials[2 * blockIdx.x]     = iou_m;
        g_partials[2 * blockIdx.x + 1] = mk;
    }
}

__global__ void poly_loss_finalize(float* __restrict__ out, int nblk) {
    float si = 0.0f, sm = 0.0f;
    for (int i = 0; i < nblk; i++) {
        si += g_partials[2 * i];
        sm += g_partials[2 * i + 1];
    }
    out[0] = 1.0f - si / (sm + 1e-6f);
}

extern "C" void kernel_launch(void* const* d_in, const int* in_sizes, int n_in,
                              void* d_out, int out_size) {
    // metadata order: output (B,2V,H,W) f32, mask (B,K) f32, ind (B,K) i32,
    //                 target (B,K,2V) f32. __output__: f32 scalar.
    const float* output = (const float*)d_in[0];
    const float* mask   = (const float*)d_in[1];
    const int*   ind    = (const int*)  d_in[2];
    const float* target = (const float*)d_in[3];
    float* out = (float*)d_out;

    // Derive dims: BK from mask; K fixed at 128 (setup), B = BK/K,
    // HW = |output| / (B * 2V * 2).
    const int BK = in_sizes[1];
    const int K  = 128;
    const int B  = BK / K;
    const int HW = (int)((long long)in_sizes[0] / ((long long)B * 2 * NV));

    const int nblk = (BK + NTHR - 1) / NTHR;   // 64 for BK=2048
    poly_loss_kernel<<<nblk, NTHR>>>(output, mask, ind, target, B, K, HW);
    poly_loss_finalize<<<1, 1>>>(out, nblk);
}

// round 13
// speedup vs baseline: 3.9073x; 3.9073x over previous
#include <cuda_runtime.h>
#include <cuda_bf16.h>

// PolyLoss: polygon IoU loss (Sutherland-Hodgman clip + shoelace area).
// B=16, K=128, V=16, C=32, HW=65536. ONE WARP PER POLYGON PAIR.
// Lane-parallel clip with ballot/popc prefix-sum compaction (bit-exact vs
// the reference's cumsum scatter). Finalize folded in via last-block pattern.

#define NV   16
#define MAXN 64          // 4*V
#define WPB  16          // warps (pairs) per block
#define NTHR (WPB * 32)
#define MAXBLK 512

__device__ float g_partials[2 * MAXBLK];
__device__ unsigned int g_count = 0;

__device__ __forceinline__ float safef(float d) {
    return (d == 0.0f) ? 1.0f : d;
}

// Sign-critical inside test: no FMA contraction (matches XLA elementwise).
__device__ __forceinline__ bool is_inside(float ex, float ey,
                                          float c1x, float c1y,
                                          float qx, float qy) {
    float a = __fmul_rn(ex, __fsub_rn(qy, c1y));
    float b = __fmul_rn(ey, __fsub_rn(qx, c1x));
    return __fsub_rn(a, b) <= 0.0f;
}

__global__ void __launch_bounds__(NTHR)
poly_loss_kernel(const float* __restrict__ output,
                 const float* __restrict__ mask,
                 const int*   __restrict__ ind,
                 const float* __restrict__ target,
                 int B, int K, int HW, int BK,
                 float* __restrict__ out)
{
    __shared__ float sbuf[WPB][4][MAXN];   // [w][0]=SX,[1]=SY,[2]=DX,[3]=DY
    __shared__ float stgt[WPB][2][NV];
    __shared__ float blk[2][WPB];
    __shared__ bool  s_last;

    const int lane = threadIdx.x & 31;
    const int w    = threadIdx.x >> 5;
    const int pair = blockIdx.x * WPB + w;

    float wi = 0.0f, wm = 0.0f;

    if (pair < BK) {
        const int C = 2 * NV;              // == 32 == warp size
        const int b = pair / K;
        const int pos = ind[pair];
        const float* obase = output + (size_t)b * C * HW + pos;
        const float* trow  = target + (size_t)pair * C;

        // lane l loads channel l (x for even l, y for odd l)
        {
            float pv = obase[(size_t)lane * HW];
            float tv = trow[lane];
            const int half = lane & 1;
            sbuf[w][half][lane >> 1] = pv;
            stgt[w][half][lane >> 1] = tv;
        }
        __syncwarp();

        float* SX = sbuf[w][0]; float* SY = sbuf[w][1];
        float* DX = sbuf[w][2]; float* DY = sbuf[w][3];
        float* TX = stgt[w][0]; float* TY = stgt[w][1];

        // ---- areas of pred & target 16-gons (doubled first edge, per ref) ----
        float lp = 0.f, rp = 0.f, lg = 0.f, rg = 0.f;
        if (lane < NV) {
            const int j = (lane + 1) & (NV - 1);
            lp = SX[lane] * SY[j];  rp = SY[lane] * SX[j];
            lg = TX[lane] * TY[j];  rg = TY[lane] * TX[j];
            if (lane == 0) {
                lp += SX[0] * SY[1];  rp += SY[0] * SX[1];
                lg += TX[0] * TY[1];  rg += TY[0] * TX[1];
            }
        }
#pragma unroll
        for (int o = 16; o > 0; o >>= 1) {
            lp += __shfl_xor_sync(0xffffffffu, lp, o);
            rp += __shfl_xor_sync(0xffffffffu, rp, o);
            lg += __shfl_xor_sync(0xffffffffu, lg, o);
            rg += __shfl_xor_sync(0xffffffffu, rg, o);
        }
        const float a_p = fabsf(0.5f * (rp - lp));
        const float a_g = fabsf(0.5f * (rg - lg));

        // ---- Sutherland-Hodgman: lane-parallel per clip edge ----
        int n = NV;
        const unsigned ltm = (1u << lane) - 1u;

        for (int e = 0; e < NV && n > 0; e++) {
            const float c1x = TX[(e + NV - 1) & (NV - 1)];
            const float c1y = TY[(e + NV - 1) & (NV - 1)];
            const float c2x = TX[e];
            const float c2y = TY[e];
            const float ex  = c2x - c1x;
            const float ey  = c2y - c1y;
            const float m2  = ey / safef(ex);
            const float b2  = c1y - m2 * c1x;
            const bool  vert2 = (ex == 0.0f);

            // chunk A: index = lane ; chunk B: index = lane + 32
            bool  eiA = false, ecA = false, eiB = false, ecB = false;
            float cxA = 0, cyA = 0, XA = 0, YA = 0;
            float cxB = 0, cyB = 0, XB = 0, YB = 0;

            {
                const int i = lane;
                if (i < n) {
                    cxA = SX[i]; cyA = SY[i];
                    const int p = (i == 0) ? n - 1 : i - 1;
                    const float px = SX[p], py = SY[p];
                    const bool ic = is_inside(ex, ey, c1x, c1y, cxA, cyA);
                    const bool ip = is_inside(ex, ey, c1x, c1y, px,  py);
                    eiA = ic ^ ip; ecA = ic;
                    if (eiA) {
                        const float dx12 = cxA - px, dy12 = cyA - py;
                        const float m1 = dy12 / safef(dx12);
                        const float b1 = py - m1 * px;
                        if (dx12 == 0.0f)      { XA = px;  YA = m2 * px  + b2; }
                        else if (vert2)        { XA = c1x; YA = m1 * c1x + b1; }
                        else { XA = (b2 - b1) / safef(m1 - m2); YA = m1 * XA + b1; }
                    }
                }
            }
            {
                const int i = lane + 32;
                if (i < n) {
                    cxB = SX[i]; cyB = SY[i];
                    const int p = i - 1;
                    const float px = SX[p], py = SY[p];
                    const bool ic = is_inside(ex, ey, c1x, c1y, cxB, cyB);
                    const bool ip = is_inside(ex, ey, c1x, c1y, px,  py);
                    eiB = ic ^ ip; ecB = ic;
                    if (eiB) {
                        const float dx12 = cxB - px, dy12 = cyB - py;
                        const float m1 = dy12 / safef(dx12);
                        const float b1 = py - m1 * px;
                        if (dx12 == 0.0f)      { XB = px;  YB = m2 * px  + b2; }
                        else if (vert2)        { XB = c1x; YB = m1 * c1x + b1; }
                        else { XB = (b2 - b1) / safef(m1 - m2); YB = m1 * XB + b1; }
                    }
                }
            }

            // exclusive prefix over 64 ordered slots (i first, then c, per index)
            const unsigned bi0 = __ballot_sync(0xffffffffu, eiA);
            const unsigned bc0 = __ballot_sync(0xffffffffu, ecA);
            const unsigned bi1 = __ballot_sync(0xffffffffu, eiB);
            const unsigned bc1 = __ballot_sync(0xffffffffu, ecB);
            const int offA = __popc(bi0 & ltm) + __popc(bc0 & ltm);
            const int tot0 = __popc(bi0) + __popc(bc0);
            const int offB = tot0 + __popc(bi1 & ltm) + __popc(bc1 & ltm);
            const int tot  = tot0 + __popc(bi1) + __popc(bc1);

            if (eiA && offA < MAXN) { DX[offA] = XA; DY[offA] = YA; }
            {
                const int oc = offA + (eiA ? 1 : 0);
                if (ecA && oc < MAXN) { DX[oc] = cxA; DY[oc] = cyA; }
            }
            if (eiB && offB < MAXN) { DX[offB] = XB; DY[offB] = YB; }
            {
                const int oc = offB + (eiB ? 1 : 0);
                if (ecB && oc < MAXN) { DX[oc] = cxB; DY[oc] = cyB; }
            }

            n = (tot < MAXN) ? tot : MAXN;
            __syncwarp();
            float* tp;
            tp = SX; SX = DX; DX = tp;
            tp = SY; SY = DY; DY = tp;
        }

        // ---- clipped-polygon area (doubled first edge) ----
        float lft = 0.f, rgt = 0.f;
#pragma unroll
        for (int c = 0; c < 2; c++) {
            const int i = lane + 32 * c;
            if (i < n) {
                const int j = (i + 1 == n) ? 0 : i + 1;
                lft += SX[i] * SY[j];
                rgt += SY[i] * SX[j];
            }
        }
        if (lane == 0 && n > 0) {
            const int i1 = (n > 1) ? 1 : 0;
            lft += SX[0] * SY[i1];
            rgt += SY[0] * SX[i1];
        }
#pragma unroll
        for (int o = 16; o > 0; o >>= 1) {
            lft += __shfl_xor_sync(0xffffffffu, lft, o);
            rgt += __shfl_xor_sync(0xffffffffu, rgt, o);
        }
        const float a_i = (n > 0) ? fabsf(0.5f * (rgt - lft)) : 0.0f;

        if (lane == 0) {
            const float inter = a_i + ((a_i == 0.0f) ? fminf(a_p, a_g) : 0.0f);
            const float uni   = a_g + a_p - inter;
            const float iou   = inter / (uni + 1e-6f);
            wm = mask[pair];
            wi = iou * wm;
        }
    }

    if (lane == 0) { blk[0][w] = wi; blk[1][w] = wm; }
    __syncthreads();

    // ---- per-block partial + last-block finalize (deterministic order) ----
    if (threadIdx.x == 0) {
        float si = 0.f, sm = 0.f;
#pragma unroll
        for (int i = 0; i < WPB; i++) { si += blk[0][i]; sm += blk[1][i]; }
        g_partials[2 * blockIdx.x]     = si;
        g_partials[2 * blockIdx.x + 1] = sm;
        __threadfence();
        const unsigned t = atomicAdd(&g_count, 1u);
        s_last = (t == gridDim.x - 1);
    }
    __syncthreads();

    if (s_last && threadIdx.x < 32) {
        const volatile float* gp = g_partials;
        float si = 0.f, sm = 0.f;
        for (int i = lane; i < (int)gridDim.x; i += 32) {
            si += gp[2 * i];
            sm += gp[2 * i + 1];
        }
#pragma unroll
        for (int o = 16; o > 0; o >>= 1) {
            si += __shfl_xor_sync(0xffffffffu, si, o);
            sm += __shfl_xor_sync(0xffffffffu, sm, o);
        }
        if (lane == 0) {
            out[0] = 1.0f - si / (sm + 1e-6f);
            g_count = 0;                 // reset for graph replay
        }
    }
}

extern "C" void kernel_launch(void* const* d_in, const int* in_sizes, int n_in,
                              void* d_out, int out_size) {
    // inputs: output (B,2V,H,W) f32, mask (B,K) f32, ind (B,K) i32,
    //         target (B,K,2V) f32. __output__: f32 scalar.
    const float* output = (const float*)d_in[0];
    const float* mask   = (const float*)d_in[1];
    const int*   ind    = (const int*)  d_in[2];
    const float* target = (const float*)d_in[3];
    float* out = (float*)d_out;

    const int BK = in_sizes[1];
    const int K  = 128;
    const int B  = BK / K;
    const int HW = (int)((long long)in_sizes[0] / ((long long)B * 2 * NV));

    int nblk = (BK + WPB - 1) / WPB;     // 128 for BK=2048
    if (nblk > MAXBLK) nblk = MAXBLK;    // (BK<=8192 covered; actual BK=2048)
    poly_loss_kernel<<<nblk, NTHR>>>(output, mask, ind, target, B, K, HW, BK, out);
}